// round 10
// baseline (speedup 1.0000x reference)
#include <cuda_runtime.h>

#define N_NODES 50000
#define N_EDGES 800000
#define CAP 96           // bucket capacity per node (Poisson(16) => P(deg>96) ~ 0)

// Scratch (device globals — no allocation allowed). 16B-aligned for vector access.
__device__ __align__(16) float g_h1[N_NODES * 128];
__device__ __align__(16) float g_a1[N_NODES * 128];
__device__ __align__(16) float g_h2[N_NODES * 64];
__device__ float g_dinv[N_NODES];
__device__ int   g_cnt[N_NODES];
__device__ int   g_cursor[N_NODES];
__device__ __align__(16) int2 g_coln[N_NODES * CAP];  // {src, norm-bits} per slot
__device__ int   g_src[N_EDGES];
__device__ int   g_dst[N_EDGES];
__device__ int   g_is64;

// Pack a float into both halves of a 64-bit reg (f32x2 broadcast)
__device__ __forceinline__ unsigned long long pack2(float v) {
    unsigned long long r;
    asm("mov.b64 %0, {%1, %1};" : "=l"(r) : "f"(v));
    return r;
}
__device__ __forceinline__ void unpack2(unsigned long long a, float& lo, float& hi) {
    asm("mov.b64 {%0, %1}, %2;" : "=f"(lo), "=f"(hi) : "l"(a));
}
#define FMA2(acc, x, w) asm("fma.rn.f32x2 %0, %1, %2, %0;" : "+l"(acc) : "l"(x), "l"(w))

// L2-only float4 load (skip L1 allocation for no-reuse gather rows)
__device__ __forceinline__ float4 ldcg4(const float4* p) {
    float4 v;
    asm("ld.global.cg.v4.f32 {%0,%1,%2,%3}, [%4];"
        : "=f"(v.x), "=f"(v.y), "=f"(v.z), "=f"(v.w) : "l"(p));
    return v;
}

// ---------------------------------------------------------------------------
// Zero counters+cursors (all blocks) + dtype detection (block 0, warp 0).
// ---------------------------------------------------------------------------
__global__ void zero_detect_kernel(const int* __restrict__ ei32) {
    int i = blockIdx.x * blockDim.x + threadIdx.x;
    if (i < N_NODES) { g_cnt[i] = 0; g_cursor[i] = 0; }
    if (blockIdx.x == 0 && threadIdx.x < 32) {
        int t = threadIdx.x;
        int nz = 0;
        for (int k = t; k < 2048; k += 32)
            if (ei32[2 * k + 1] != 0) nz = 1;
        #pragma unroll
        for (int o = 16; o; o >>= 1) nz |= __shfl_xor_sync(0xffffffffu, nz, o);
        if (t == 0) g_is64 = (nz == 0) ? 1 : 0;
    }
}

// Decode (clamped) + degree count in one pass.
__global__ void decode_count_kernel(const void* __restrict__ ei) {
    int e = blockIdx.x * blockDim.x + threadIdx.x;
    if (e >= N_EDGES) return;
    int s, d;
    if (g_is64) {
        const long long* p = (const long long*)ei;
        s = (int)p[e];
        d = (int)p[N_EDGES + e];
    } else {
        const int* p = (const int*)ei;
        s = p[e];
        d = p[N_EDGES + e];
    }
    s = min(max(s, 0), N_NODES - 1);
    d = min(max(d, 0), N_NODES - 1);
    g_src[e] = s;
    g_dst[e] = d;
    atomicAdd(&g_cnt[d], 1);
}

// dinv from final degrees.
__global__ void dinv_kernel() {
    int i = blockIdx.x * blockDim.x + threadIdx.x;
    if (i < N_NODES) g_dinv[i] = rsqrtf((float)(g_cnt[i] + 1));
}

// Fill fixed-capacity buckets with {src, norm = dinv[s]*dinv[d]}. No scan needed.
__global__ void fill_kernel() {
    int e = blockIdx.x * blockDim.x + threadIdx.x;
    if (e >= N_EDGES) return;
    int s = g_src[e];
    int d = g_dst[e];
    int pos = atomicAdd(&g_cursor[d], 1);
    if (pos < CAP) {
        float nm = g_dinv[s] * g_dinv[d];
        g_coln[d * CAP + pos] = make_int2(s, __float_as_int(nm));
    }
}

// ---------------------------------------------------------------------------
// FFMA2 GEMM: tile M=64 rows, N=64 cols, K=128. X duplicated into smem as
// (x,x) u64 pairs: mainloop = LDS.64 bcast + LDS.128 + 8 FFMA2, zero MOVs.
// ---------------------------------------------------------------------------
#define XD_STRIDE 130
#define GEMM_SMEM (64 * XD_STRIDE * 8 + 128 * 64 * 4)

template <int WSTRIDE, bool RELU, bool LAYER1>
__global__ void __launch_bounds__(256) gemm_kernel(const float* __restrict__ Xin,
                                                   const float* __restrict__ W) {
    extern __shared__ __align__(16) unsigned char smem_raw[];
    unsigned long long* Xd = (unsigned long long*)smem_raw;          // [64][130]
    float* Ws = (float*)(smem_raw + 64 * XD_STRIDE * 8);             // [128][64]

    const float* X = LAYER1 ? Xin : (const float*)g_a1;  // both stride 128
    float* H = LAYER1 ? g_h1 : g_h2;

    const int tid = threadIdx.x;
    const int rowBase = blockIdx.x * 64;
    const int colBase = blockIdx.y * 64;

    #pragma unroll
    for (int i = 0; i < 8; i++) {
        int idx = tid + i * 256;            // (row, k4): 64*32
        int row = idx >> 5, k4 = (idx & 31) * 4;
        int grow = min(rowBase + row, N_NODES - 1);
        float4 v = *(const float4*)(X + (size_t)grow * 128 + k4);
        if (RELU) {
            v.x = fmaxf(v.x, 0.f); v.y = fmaxf(v.y, 0.f);
            v.z = fmaxf(v.z, 0.f); v.w = fmaxf(v.w, 0.f);
        }
        unsigned long long* p = &Xd[row * XD_STRIDE + k4];
        ((ulonglong2*)p)[0] = make_ulonglong2(pack2(v.x), pack2(v.y));
        ((ulonglong2*)p)[1] = make_ulonglong2(pack2(v.z), pack2(v.w));
    }
    #pragma unroll
    for (int i = 0; i < 8; i++) {
        int idx = tid + i * 256;            // (k, c4): 128*16
        int k = idx >> 4, c4 = (idx & 15) * 4;
        *(float4*)&Ws[k * 64 + c4] = *(const float4*)(W + k * WSTRIDE + colBase + c4);
    }
    __syncthreads();

    const int ty = tid >> 4;
    const int tx = tid & 15;
    unsigned long long acc[4][2];
    #pragma unroll
    for (int r = 0; r < 4; r++) { acc[r][0] = 0ull; acc[r][1] = 0ull; }

    const unsigned long long* xb = &Xd[ty * 4 * XD_STRIDE];
    const float* wb = &Ws[tx * 4];

    #pragma unroll 4
    for (int k = 0; k < 128; k++) {
        ulonglong2 w2 = *(const ulonglong2*)(wb + k * 64);
        #pragma unroll
        for (int r = 0; r < 4; r++) {
            unsigned long long xp = xb[r * XD_STRIDE + k];
            FMA2(acc[r][0], xp, w2.x);
            FMA2(acc[r][1], xp, w2.y);
        }
    }

    #pragma unroll
    for (int r = 0; r < 4; r++) {
        int grow = rowBase + ty * 4 + r;
        if (grow < N_NODES) {
            float4 o;
            unpack2(acc[r][0], o.x, o.y);
            unpack2(acc[r][1], o.z, o.w);
            *(float4*)&H[(size_t)grow * WSTRIDE + colBase + tx * 4] = o;
        }
    }
}

// FMA a float4 row into acc with scalar norm
#define ROWFMA(acc, v, nm) \
    acc.x = fmaf(v.x, nm, acc.x); acc.y = fmaf(v.y, nm, acc.y); \
    acc.z = fmaf(v.z, nm, acc.z); acc.w = fmaf(v.w, nm, acc.w)

// ---------------------------------------------------------------------------
// Layer-1 aggregation by gather (D=128, one node per warp), 4-way ILP.
// ---------------------------------------------------------------------------
__global__ void agg128_kernel(const float* __restrict__ b) {
    int n = (blockIdx.x * blockDim.x + threadIdx.x) >> 5;
    int l = threadIdx.x & 31;
    if (n >= N_NODES) return;

    int beg = n * CAP;
    int cnt = min(g_cnt[n], CAP);
    float din = g_dinv[n];

    float4 h = ((const float4*)(g_h1 + (size_t)n * 128))[l];
    float4 bb = ((const float4*)b)[l];
    float w = din * din;
    float4 acc;
    acc.x = fmaf(h.x, w, bb.x);
    acc.y = fmaf(h.y, w, bb.y);
    acc.z = fmaf(h.z, w, bb.z);
    acc.w = fmaf(h.w, w, bb.w);

    int i = 0;
    for (; i + 4 <= cnt; i += 4) {
        int2 c0 = g_coln[beg + i];
        int2 c1 = g_coln[beg + i + 1];
        int2 c2 = g_coln[beg + i + 2];
        int2 c3 = g_coln[beg + i + 3];
        float4 v0 = ldcg4((const float4*)(g_h1 + (size_t)c0.x * 128) + l);
        float4 v1 = ldcg4((const float4*)(g_h1 + (size_t)c1.x * 128) + l);
        float4 v2 = ldcg4((const float4*)(g_h1 + (size_t)c2.x * 128) + l);
        float4 v3 = ldcg4((const float4*)(g_h1 + (size_t)c3.x * 128) + l);
        ROWFMA(acc, v0, __int_as_float(c0.y));
        ROWFMA(acc, v1, __int_as_float(c1.y));
        ROWFMA(acc, v2, __int_as_float(c2.y));
        ROWFMA(acc, v3, __int_as_float(c3.y));
    }
    for (; i < cnt; i++) {
        int2 c0 = g_coln[beg + i];
        float4 v0 = ldcg4((const float4*)(g_h1 + (size_t)c0.x * 128) + l);
        ROWFMA(acc, v0, __int_as_float(c0.y));
    }

    ((float4*)(g_a1 + (size_t)n * 128))[l] = acc;
}

// ---------------------------------------------------------------------------
// Layer-2 aggregation (D=64, 2 nodes per warp) FUSED with log_softmax, 4-way ILP.
// ---------------------------------------------------------------------------
__global__ void agg64_softmax_kernel(const float* __restrict__ b,
                                     float* __restrict__ out) {
    int gw = (blockIdx.x * blockDim.x + threadIdx.x) >> 5;
    int lane = threadIdx.x & 31;
    int n = gw * 2 + (lane >> 4);
    int l = lane & 15;
    if (n >= N_NODES) return;

    int beg = n * CAP;
    int cnt = min(g_cnt[n], CAP);
    float din = g_dinv[n];

    float4 h = ((const float4*)(g_h2 + (size_t)n * 64))[l];
    float4 bb = ((const float4*)b)[l];
    float w = din * din;
    float4 acc;
    acc.x = fmaf(h.x, w, bb.x);
    acc.y = fmaf(h.y, w, bb.y);
    acc.z = fmaf(h.z, w, bb.z);
    acc.w = fmaf(h.w, w, bb.w);

    int i = 0;
    for (; i + 4 <= cnt; i += 4) {
        int2 c0 = g_coln[beg + i];
        int2 c1 = g_coln[beg + i + 1];
        int2 c2 = g_coln[beg + i + 2];
        int2 c3 = g_coln[beg + i + 3];
        float4 v0 = ldcg4((const float4*)(g_h2 + (size_t)c0.x * 64) + l);
        float4 v1 = ldcg4((const float4*)(g_h2 + (size_t)c1.x * 64) + l);
        float4 v2 = ldcg4((const float4*)(g_h2 + (size_t)c2.x * 64) + l);
        float4 v3 = ldcg4((const float4*)(g_h2 + (size_t)c3.x * 64) + l);
        ROWFMA(acc, v0, __int_as_float(c0.y));
        ROWFMA(acc, v1, __int_as_float(c1.y));
        ROWFMA(acc, v2, __int_as_float(c2.y));
        ROWFMA(acc, v3, __int_as_float(c3.y));
    }
    for (; i < cnt; i++) {
        int2 c0 = g_coln[beg + i];
        float4 v0 = ldcg4((const float4*)(g_h2 + (size_t)c0.x * 64) + l);
        ROWFMA(acc, v0, __int_as_float(c0.y));
    }

    // log_softmax over the 64 values of node n (16 lanes x 4)
    float m = fmaxf(fmaxf(acc.x, acc.y), fmaxf(acc.z, acc.w));
    #pragma unroll
    for (int o = 8; o; o >>= 1) m = fmaxf(m, __shfl_xor_sync(0xffffffffu, m, o, 16));
    float s = expf(acc.x - m) + expf(acc.y - m) + expf(acc.z - m) + expf(acc.w - m);
    #pragma unroll
    for (int o = 8; o; o >>= 1) s += __shfl_xor_sync(0xffffffffu, s, o, 16);
    float ls = m + logf(s);

    float4 r;
    r.x = acc.x - ls; r.y = acc.y - ls; r.z = acc.z - ls; r.w = acc.w - ls;
    ((float4*)(out + (size_t)n * 64))[l] = r;
}

// ---------------------------------------------------------------------------
extern "C" void kernel_launch(void* const* d_in, const int* in_sizes, int n_in,
                              void* d_out, int out_size) {
    // Bind inputs by UNIQUE element count (ordering/dtype robust).
    const float* x = nullptr;
    const void* ei = nullptr;
    const float *W1 = nullptr, *b1 = nullptr, *W2 = nullptr, *b2 = nullptr;
    for (int i = 0; i < n_in; i++) {
        switch (in_sizes[i]) {
            case 6400000: x  = (const float*)d_in[i]; break;
            case 1600000: ei = d_in[i]; break;
            case 16384:   W1 = (const float*)d_in[i]; break;
            case 128:     b1 = (const float*)d_in[i]; break;
            case 8192:    W2 = (const float*)d_in[i]; break;
            case 64:      b2 = (const float*)d_in[i]; break;
        }
    }
    float* out = (float*)d_out;

    // One-time host-side resources (no device memory involved).
    static cudaStream_t side = nullptr;
    static cudaEvent_t evFork = nullptr, evJoin = nullptr;
    if (!side) {
        cudaStreamCreateWithFlags(&side, cudaStreamNonBlocking);
        cudaEventCreateWithFlags(&evFork, cudaEventDisableTiming);
        cudaEventCreateWithFlags(&evJoin, cudaEventDisableTiming);
        cudaFuncSetAttribute(gemm_kernel<128, false, true>,
                             cudaFuncAttributeMaxDynamicSharedMemorySize, GEMM_SMEM);
        cudaFuncSetAttribute(gemm_kernel<64, true, false>,
                             cudaFuncAttributeMaxDynamicSharedMemorySize, GEMM_SMEM);
    }

    const int NB = (N_NODES + 255) / 256;  // 196
    const int EB = (N_EDGES + 255) / 256;

    // Fork: bucket-CSR build on side stream (4 launches), gemm1 on main stream.
    cudaEventRecord(evFork, 0);
    cudaStreamWaitEvent(side, evFork, 0);

    zero_detect_kernel<<<NB, 256, 0, side>>>((const int*)ei);
    decode_count_kernel<<<EB, 256, 0, side>>>(ei);
    dinv_kernel<<<NB, 256, 0, side>>>();
    fill_kernel<<<EB, 256, 0, side>>>();
    cudaEventRecord(evJoin, side);

    gemm_kernel<128, false, true><<<dim3(782, 2), 256, GEMM_SMEM>>>(x, W1);

    // Join: agg128 needs both gemm1 (h1) and the bucket CSR.
    cudaStreamWaitEvent(0, evJoin, 0);
    agg128_kernel<<<(N_NODES * 32 + 255) / 256, 256>>>(b1);

    gemm_kernel<64, true, false><<<dim3(782, 1), 256, GEMM_SMEM>>>(nullptr, W2);
    agg64_softmax_kernel<<<(N_NODES * 16 + 255) / 256, 256>>>(b2, out);
}

// round 11
// speedup vs baseline: 1.0696x; 1.0696x over previous
#include <cuda_runtime.h>
#include <cuda_fp16.h>

#define N_NODES 50000
#define N_EDGES 800000
#define SCAN_BLOCKS 196  // ceil(50000/256)

// Scratch (device globals — no allocation allowed). 16B-aligned for vector access.
__device__ __align__(16) __half g_h1h[N_NODES * 128];  // layer1 product, fp16
__device__ __align__(16) float  g_a1[N_NODES * 128];   // layer1 aggregated, fp32
__device__ __align__(16) __half g_h2h[N_NODES * 64];   // layer2 product, fp16
__device__ float g_dinv[N_NODES];
__device__ int   g_cnt[N_NODES];
__device__ int   g_rowoff[N_NODES];
__device__ int   g_cursor[N_NODES];
__device__ __align__(16) int2 g_coln[N_EDGES];  // {src, norm-bits} per CSR slot
__device__ int   g_src[N_EDGES];
__device__ int   g_dst[N_EDGES];
__device__ int   g_blocksum[SCAN_BLOCKS];
__device__ int   g_blockoff[SCAN_BLOCKS];
__device__ int   g_is64;

// Pack a float into both halves of a 64-bit reg (f32x2 broadcast)
__device__ __forceinline__ unsigned long long pack2(float v) {
    unsigned long long r;
    asm("mov.b64 %0, {%1, %1};" : "=l"(r) : "f"(v));
    return r;
}
__device__ __forceinline__ void unpack2(unsigned long long a, float& lo, float& hi) {
    asm("mov.b64 {%0, %1}, %2;" : "=f"(lo), "=f"(hi) : "l"(a));
}
#define FMA2(acc, x, w) asm("fma.rn.f32x2 %0, %1, %2, %0;" : "+l"(acc) : "l"(x), "l"(w))

// L2-only 8-byte load (4 halves) — skip L1 for no-reuse gather rows
__device__ __forceinline__ uint2 ldcg2(const uint2* p) {
    uint2 v;
    asm("ld.global.cg.v2.u32 {%0,%1}, [%2];" : "=r"(v.x), "=r"(v.y) : "l"(p));
    return v;
}
// 4 halves (as uint2) -> float4
__device__ __forceinline__ float4 h4_to_f4(uint2 r) {
    float2 a = __half22float2(*(__half2*)&r.x);
    float2 b = __half22float2(*(__half2*)&r.y);
    return make_float4(a.x, a.y, b.x, b.y);
}

// ---------------------------------------------------------------------------
// Zero counters (all blocks) + dtype detection (block 0, warp 0).
// ---------------------------------------------------------------------------
__global__ void zero_detect_kernel(const int* __restrict__ ei32) {
    int i = blockIdx.x * blockDim.x + threadIdx.x;
    if (i < N_NODES) g_cnt[i] = 0;
    if (blockIdx.x == 0 && threadIdx.x < 32) {
        int t = threadIdx.x;
        int nz = 0;
        for (int k = t; k < 2048; k += 32)
            if (ei32[2 * k + 1] != 0) nz = 1;
        #pragma unroll
        for (int o = 16; o; o >>= 1) nz |= __shfl_xor_sync(0xffffffffu, nz, o);
        if (t == 0) g_is64 = (nz == 0) ? 1 : 0;
    }
}

// Decode (clamped) + degree count in one pass.
__global__ void decode_count_kernel(const void* __restrict__ ei) {
    int e = blockIdx.x * blockDim.x + threadIdx.x;
    if (e >= N_EDGES) return;
    int s, d;
    if (g_is64) {
        const long long* p = (const long long*)ei;
        s = (int)p[e];
        d = (int)p[N_EDGES + e];
    } else {
        const int* p = (const int*)ei;
        s = p[e];
        d = p[N_EDGES + e];
    }
    s = min(max(s, 0), N_NODES - 1);
    d = min(max(d, 0), N_NODES - 1);
    g_src[e] = s;
    g_dst[e] = d;
    atomicAdd(&g_cnt[d], 1);
}

__global__ void scan1_kernel() {
    __shared__ int s[256];
    int t = threadIdx.x;
    int i = blockIdx.x * 256 + t;
    int v = (i < N_NODES) ? g_cnt[i] : 0;
    s[t] = v;
    __syncthreads();
    #pragma unroll
    for (int off = 1; off < 256; off <<= 1) {
        int add = (t >= off) ? s[t - off] : 0;
        __syncthreads();
        s[t] += add;
        __syncthreads();
    }
    if (i < N_NODES) g_rowoff[i] = s[t] - v;  // block-local exclusive
    if (t == 255) g_blocksum[blockIdx.x] = s[255];
}

__global__ void scan2_kernel() {  // single 256-thread block over 196 sums
    __shared__ int s[256];
    int t = threadIdx.x;
    int v = (t < SCAN_BLOCKS) ? g_blocksum[t] : 0;
    s[t] = v;
    __syncthreads();
    #pragma unroll
    for (int off = 1; off < 256; off <<= 1) {
        int add = (t >= off) ? s[t - off] : 0;
        __syncthreads();
        s[t] += add;
        __syncthreads();
    }
    if (t < SCAN_BLOCKS) g_blockoff[t] = s[t] - v;
}

// Grid-wide: finalize rowoff, init cursor=rowoff, compute dinv (needed by fill).
__global__ void scan3_kernel() {
    int i = blockIdx.x * blockDim.x + threadIdx.x;
    if (i >= N_NODES) return;
    int ro = g_rowoff[i] + g_blockoff[blockIdx.x];  // blockDim=256 matches scan1
    g_rowoff[i] = ro;
    g_cursor[i] = ro;
    g_dinv[i] = rsqrtf((float)(g_cnt[i] + 1));
}

// Fill CSR slots with {src, precomputed edge norm = dinv[s]*dinv[d]}.
__global__ void fill_kernel() {
    int e = blockIdx.x * blockDim.x + threadIdx.x;
    if (e >= N_EDGES) return;
    int s = g_src[e];
    int d = g_dst[e];
    int pos = atomicAdd(&g_cursor[d], 1);
    float nm = g_dinv[s] * g_dinv[d];
    g_coln[pos] = make_int2(s, __float_as_int(nm));
}

// ---------------------------------------------------------------------------
// FFMA2 GEMM: tile M=64 rows, N=64 cols, K=128; output stored as fp16.
// X duplicated into smem as (x,x) u64 pairs: zero-MOV mainloop.
// ---------------------------------------------------------------------------
#define XD_STRIDE 130
#define GEMM_SMEM (64 * XD_STRIDE * 8 + 128 * 64 * 4)

template <int WSTRIDE, bool RELU, bool LAYER1>
__global__ void __launch_bounds__(256) gemm_kernel(const float* __restrict__ Xin,
                                                   const float* __restrict__ W) {
    extern __shared__ __align__(16) unsigned char smem_raw[];
    unsigned long long* Xd = (unsigned long long*)smem_raw;          // [64][130]
    float* Ws = (float*)(smem_raw + 64 * XD_STRIDE * 8);             // [128][64]

    const float* X = LAYER1 ? Xin : (const float*)g_a1;  // both stride 128
    __half* H = LAYER1 ? g_h1h : g_h2h;

    const int tid = threadIdx.x;
    const int rowBase = blockIdx.x * 64;
    const int colBase = blockIdx.y * 64;

    #pragma unroll
    for (int i = 0; i < 8; i++) {
        int idx = tid + i * 256;            // (row, k4): 64*32
        int row = idx >> 5, k4 = (idx & 31) * 4;
        int grow = min(rowBase + row, N_NODES - 1);
        float4 v = *(const float4*)(X + (size_t)grow * 128 + k4);
        if (RELU) {
            v.x = fmaxf(v.x, 0.f); v.y = fmaxf(v.y, 0.f);
            v.z = fmaxf(v.z, 0.f); v.w = fmaxf(v.w, 0.f);
        }
        unsigned long long* p = &Xd[row * XD_STRIDE + k4];
        ((ulonglong2*)p)[0] = make_ulonglong2(pack2(v.x), pack2(v.y));
        ((ulonglong2*)p)[1] = make_ulonglong2(pack2(v.z), pack2(v.w));
    }
    #pragma unroll
    for (int i = 0; i < 8; i++) {
        int idx = tid + i * 256;            // (k, c4): 128*16
        int k = idx >> 4, c4 = (idx & 15) * 4;
        *(float4*)&Ws[k * 64 + c4] = *(const float4*)(W + k * WSTRIDE + colBase + c4);
    }
    __syncthreads();

    const int ty = tid >> 4;
    const int tx = tid & 15;
    unsigned long long acc[4][2];
    #pragma unroll
    for (int r = 0; r < 4; r++) { acc[r][0] = 0ull; acc[r][1] = 0ull; }

    const unsigned long long* xb = &Xd[ty * 4 * XD_STRIDE];
    const float* wb = &Ws[tx * 4];

    #pragma unroll 4
    for (int k = 0; k < 128; k++) {
        ulonglong2 w2 = *(const ulonglong2*)(wb + k * 64);
        #pragma unroll
        for (int r = 0; r < 4; r++) {
            unsigned long long xp = xb[r * XD_STRIDE + k];
            FMA2(acc[r][0], xp, w2.x);
            FMA2(acc[r][1], xp, w2.y);
        }
    }

    #pragma unroll
    for (int r = 0; r < 4; r++) {
        int grow = rowBase + ty * 4 + r;
        if (grow < N_NODES) {
            float4 o;
            unpack2(acc[r][0], o.x, o.y);
            unpack2(acc[r][1], o.z, o.w);
            __half2 p0 = __float22half2_rn(make_float2(o.x, o.y));
            __half2 p1 = __float22half2_rn(make_float2(o.z, o.w));
            uint2 st;
            st.x = *(unsigned*)&p0;
            st.y = *(unsigned*)&p1;
            *(uint2*)&H[(size_t)grow * WSTRIDE + colBase + tx * 4] = st;
        }
    }
}

// FMA a float4 row into acc with scalar norm
#define ROWFMA(acc, v, nm) \
    acc.x = fmaf(v.x, nm, acc.x); acc.y = fmaf(v.y, nm, acc.y); \
    acc.z = fmaf(v.z, nm, acc.z); acc.w = fmaf(v.w, nm, acc.w)

// ---------------------------------------------------------------------------
// Layer-1 aggregation by fp16 gather (D=128, one node per warp), 4-way ILP.
// Accumulate fp32, write a1 fp32.
// ---------------------------------------------------------------------------
__global__ void agg128_kernel(const float* __restrict__ b) {
    int n = (blockIdx.x * blockDim.x + threadIdx.x) >> 5;
    int l = threadIdx.x & 31;
    if (n >= N_NODES) return;

    int beg = g_rowoff[n];
    int cnt = g_cnt[n];
    float din = g_dinv[n];

    float4 h = h4_to_f4(((const uint2*)(g_h1h + (size_t)n * 128))[l]);
    float4 bb = ((const float4*)b)[l];
    float w = din * din;
    float4 acc;
    acc.x = fmaf(h.x, w, bb.x);
    acc.y = fmaf(h.y, w, bb.y);
    acc.z = fmaf(h.z, w, bb.z);
    acc.w = fmaf(h.w, w, bb.w);

    int i = 0;
    for (; i + 4 <= cnt; i += 4) {
        int2 c0 = g_coln[beg + i];
        int2 c1 = g_coln[beg + i + 1];
        int2 c2 = g_coln[beg + i + 2];
        int2 c3 = g_coln[beg + i + 3];
        uint2 r0 = ldcg2((const uint2*)(g_h1h + (size_t)c0.x * 128) + l);
        uint2 r1 = ldcg2((const uint2*)(g_h1h + (size_t)c1.x * 128) + l);
        uint2 r2 = ldcg2((const uint2*)(g_h1h + (size_t)c2.x * 128) + l);
        uint2 r3 = ldcg2((const uint2*)(g_h1h + (size_t)c3.x * 128) + l);
        float4 v0 = h4_to_f4(r0);
        float4 v1 = h4_to_f4(r1);
        float4 v2 = h4_to_f4(r2);
        float4 v3 = h4_to_f4(r3);
        ROWFMA(acc, v0, __int_as_float(c0.y));
        ROWFMA(acc, v1, __int_as_float(c1.y));
        ROWFMA(acc, v2, __int_as_float(c2.y));
        ROWFMA(acc, v3, __int_as_float(c3.y));
    }
    for (; i < cnt; i++) {
        int2 c0 = g_coln[beg + i];
        float4 v0 = h4_to_f4(ldcg2((const uint2*)(g_h1h + (size_t)c0.x * 128) + l));
        ROWFMA(acc, v0, __int_as_float(c0.y));
    }

    ((float4*)(g_a1 + (size_t)n * 128))[l] = acc;
}

// ---------------------------------------------------------------------------
// Layer-2 fp16 aggregation (D=64, 2 nodes per warp) FUSED with log_softmax.
// ---------------------------------------------------------------------------
__global__ void agg64_softmax_kernel(const float* __restrict__ b,
                                     float* __restrict__ out) {
    int gw = (blockIdx.x * blockDim.x + threadIdx.x) >> 5;
    int lane = threadIdx.x & 31;
    int n = gw * 2 + (lane >> 4);
    int l = lane & 15;
    if (n >= N_NODES) return;

    int beg = g_rowoff[n];
    int cnt = g_cnt[n];
    float din = g_dinv[n];

    float4 h = h4_to_f4(((const uint2*)(g_h2h + (size_t)n * 64))[l]);
    float4 bb = ((const float4*)b)[l];
    float w = din * din;
    float4 acc;
    acc.x = fmaf(h.x, w, bb.x);
    acc.y = fmaf(h.y, w, bb.y);
    acc.z = fmaf(h.z, w, bb.z);
    acc.w = fmaf(h.w, w, bb.w);

    int i = 0;
    for (; i + 4 <= cnt; i += 4) {
        int2 c0 = g_coln[beg + i];
        int2 c1 = g_coln[beg + i + 1];
        int2 c2 = g_coln[beg + i + 2];
        int2 c3 = g_coln[beg + i + 3];
        uint2 r0 = ldcg2((const uint2*)(g_h2h + (size_t)c0.x * 64) + l);
        uint2 r1 = ldcg2((const uint2*)(g_h2h + (size_t)c1.x * 64) + l);
        uint2 r2 = ldcg2((const uint2*)(g_h2h + (size_t)c2.x * 64) + l);
        uint2 r3 = ldcg2((const uint2*)(g_h2h + (size_t)c3.x * 64) + l);
        float4 v0 = h4_to_f4(r0);
        float4 v1 = h4_to_f4(r1);
        float4 v2 = h4_to_f4(r2);
        float4 v3 = h4_to_f4(r3);
        ROWFMA(acc, v0, __int_as_float(c0.y));
        ROWFMA(acc, v1, __int_as_float(c1.y));
        ROWFMA(acc, v2, __int_as_float(c2.y));
        ROWFMA(acc, v3, __int_as_float(c3.y));
    }
    for (; i < cnt; i++) {
        int2 c0 = g_coln[beg + i];
        float4 v0 = h4_to_f4(ldcg2((const uint2*)(g_h2h + (size_t)c0.x * 64) + l));
        ROWFMA(acc, v0, __int_as_float(c0.y));
    }

    // log_softmax over the 64 values of node n (16 lanes x 4)
    float m = fmaxf(fmaxf(acc.x, acc.y), fmaxf(acc.z, acc.w));
    #pragma unroll
    for (int o = 8; o; o >>= 1) m = fmaxf(m, __shfl_xor_sync(0xffffffffu, m, o, 16));
    float s = expf(acc.x - m) + expf(acc.y - m) + expf(acc.z - m) + expf(acc.w - m);
    #pragma unroll
    for (int o = 8; o; o >>= 1) s += __shfl_xor_sync(0xffffffffu, s, o, 16);
    float ls = m + logf(s);

    float4 r;
    r.x = acc.x - ls; r.y = acc.y - ls; r.z = acc.z - ls; r.w = acc.w - ls;
    ((float4*)(out + (size_t)n * 64))[l] = r;
}

// ---------------------------------------------------------------------------
extern "C" void kernel_launch(void* const* d_in, const int* in_sizes, int n_in,
                              void* d_out, int out_size) {
    // Bind inputs by UNIQUE element count (ordering/dtype robust).
    const float* x = nullptr;
    const void* ei = nullptr;
    const float *W1 = nullptr, *b1 = nullptr, *W2 = nullptr, *b2 = nullptr;
    for (int i = 0; i < n_in; i++) {
        switch (in_sizes[i]) {
            case 6400000: x  = (const float*)d_in[i]; break;
            case 1600000: ei = d_in[i]; break;
            case 16384:   W1 = (const float*)d_in[i]; break;
            case 128:     b1 = (const float*)d_in[i]; break;
            case 8192:    W2 = (const float*)d_in[i]; break;
            case 64:      b2 = (const float*)d_in[i]; break;
        }
    }
    float* out = (float*)d_out;

    // One-time host-side resources (no device memory involved).
    static cudaStream_t side = nullptr;
    static cudaEvent_t evFork = nullptr, evJoin = nullptr;
    if (!side) {
        cudaStreamCreateWithFlags(&side, cudaStreamNonBlocking);
        cudaEventCreateWithFlags(&evFork, cudaEventDisableTiming);
        cudaEventCreateWithFlags(&evJoin, cudaEventDisableTiming);
        cudaFuncSetAttribute(gemm_kernel<128, false, true>,
                             cudaFuncAttributeMaxDynamicSharedMemorySize, GEMM_SMEM);
        cudaFuncSetAttribute(gemm_kernel<64, true, false>,
                             cudaFuncAttributeMaxDynamicSharedMemorySize, GEMM_SMEM);
    }

    const int NB = (N_NODES + 255) / 256;  // 196
    const int EB = (N_EDGES + 255) / 256;

    // Fork: CSR build chain on side stream, gemm1 on main stream (independent).
    cudaEventRecord(evFork, 0);
    cudaStreamWaitEvent(side, evFork, 0);

    zero_detect_kernel<<<NB, 256, 0, side>>>((const int*)ei);
    decode_count_kernel<<<EB, 256, 0, side>>>(ei);
    scan1_kernel<<<SCAN_BLOCKS, 256, 0, side>>>();
    scan2_kernel<<<1, 256, 0, side>>>();
    scan3_kernel<<<SCAN_BLOCKS, 256, 0, side>>>();
    fill_kernel<<<EB, 256, 0, side>>>();
    cudaEventRecord(evJoin, side);

    gemm_kernel<128, false, true><<<dim3(782, 2), 256, GEMM_SMEM>>>(x, W1);

    // Join: agg128 needs both gemm1 (h1) and the CSR structures.
    cudaStreamWaitEvent(0, evJoin, 0);
    agg128_kernel<<<(N_NODES * 32 + 255) / 256, 256>>>(b1);

    gemm_kernel<64, true, false><<<dim3(782, 1), 256, GEMM_SMEM>>>(nullptr, W2);
    agg64_softmax_kernel<<<(N_NODES * 16 + 255) / 256, 256>>>(b2, out);
}

// round 12
// speedup vs baseline: 1.1210x; 1.0480x over previous
#include <cuda_runtime.h>
#include <cuda_fp16.h>

#define N_NODES 50000
#define N_EDGES 800000

// Scratch (device globals — no allocation allowed). 16B-aligned for vector access.
__device__ __align__(16) __half g_h1h[N_NODES * 128];  // layer1 product, fp16
__device__ __align__(16) __half g_a1h[N_NODES * 128];  // layer1 aggregated, fp16
__device__ __align__(16) __half g_h2h[N_NODES * 64];   // layer2 product, fp16
__device__ float g_dinv[N_NODES];
__device__ int   g_cnt[N_NODES];
__device__ int   g_rowoff[N_NODES];
__device__ int   g_cursor[N_NODES];
__device__ __align__(16) int2 g_coln[N_EDGES];  // {src, norm-bits} per CSR slot
__device__ int   g_src[N_EDGES];
__device__ int   g_dst[N_EDGES];
__device__ int   g_total;
__device__ int   g_is64;

// Pack a float into both halves of a 64-bit reg (f32x2 broadcast)
__device__ __forceinline__ unsigned long long pack2(float v) {
    unsigned long long r;
    asm("mov.b64 %0, {%1, %1};" : "=l"(r) : "f"(v));
    return r;
}
__device__ __forceinline__ void unpack2(unsigned long long a, float& lo, float& hi) {
    asm("mov.b64 {%0, %1}, %2;" : "=f"(lo), "=f"(hi) : "l"(a));
}
#define FMA2(acc, x, w) asm("fma.rn.f32x2 %0, %1, %2, %0;" : "+l"(acc) : "l"(x), "l"(w))

// L2-only 8-byte load (4 halves) — skip L1 for no-reuse gather rows
__device__ __forceinline__ uint2 ldcg2(const uint2* p) {
    uint2 v;
    asm("ld.global.cg.v2.u32 {%0,%1}, [%2];" : "=r"(v.x), "=r"(v.y) : "l"(p));
    return v;
}
// 4 halves (as uint2) -> float4
__device__ __forceinline__ float4 h4_to_f4(uint2 r) {
    float2 a = __half22float2(*(__half2*)&r.x);
    float2 b = __half22float2(*(__half2*)&r.y);
    return make_float4(a.x, a.y, b.x, b.y);
}
// float4 -> 4 halves (as uint2)
__device__ __forceinline__ uint2 f4_to_h4(float4 v) {
    __half2 p0 = __float22half2_rn(make_float2(v.x, v.y));
    __half2 p1 = __float22half2_rn(make_float2(v.z, v.w));
    uint2 r;
    r.x = *(unsigned*)&p0;
    r.y = *(unsigned*)&p1;
    return r;
}

// ---------------------------------------------------------------------------
// Zero counters + global cursor (all blocks) + dtype detection (block 0 warp 0).
// ---------------------------------------------------------------------------
__global__ void zero_detect_kernel(const int* __restrict__ ei32) {
    int i = blockIdx.x * blockDim.x + threadIdx.x;
    if (i < N_NODES) g_cnt[i] = 0;
    if (i == 0) g_total = 0;
    if (blockIdx.x == 0 && threadIdx.x < 32) {
        int t = threadIdx.x;
        int nz = 0;
        for (int k = t; k < 2048; k += 32)
            if (ei32[2 * k + 1] != 0) nz = 1;
        #pragma unroll
        for (int o = 16; o; o >>= 1) nz |= __shfl_xor_sync(0xffffffffu, nz, o);
        if (t == 0) g_is64 = (nz == 0) ? 1 : 0;
    }
}

// Decode (clamped) + degree count in one pass.
__global__ void decode_count_kernel(const void* __restrict__ ei) {
    int e = blockIdx.x * blockDim.x + threadIdx.x;
    if (e >= N_EDGES) return;
    int s, d;
    if (g_is64) {
        const long long* p = (const long long*)ei;
        s = (int)p[e];
        d = (int)p[N_EDGES + e];
    } else {
        const int* p = (const int*)ei;
        s = p[e];
        d = p[N_EDGES + e];
    }
    s = min(max(s, 0), N_NODES - 1);
    d = min(max(d, 0), N_NODES - 1);
    g_src[e] = s;
    g_dst[e] = d;
    atomicAdd(&g_cnt[d], 1);
}

// ---------------------------------------------------------------------------
// Slot allocation: block-local inclusive scan + ONE atomicAdd per block.
// Row offsets are unordered across blocks — harmless: per-node slot ranges are
// disjoint and summation order is already nondeterministic via fill's atomics.
// Also computes cursor=rowoff and dinv. Replaces scan1+scan2+scan3.
// ---------------------------------------------------------------------------
__global__ void alloc_kernel() {
    __shared__ int s[256];
    __shared__ int base;
    int t = threadIdx.x;
    int i = blockIdx.x * 256 + t;
    int v = (i < N_NODES) ? g_cnt[i] : 0;
    s[t] = v;
    __syncthreads();
    #pragma unroll
    for (int off = 1; off < 256; off <<= 1) {
        int add = (t >= off) ? s[t - off] : 0;
        __syncthreads();
        s[t] += add;
        __syncthreads();
    }
    if (t == 255) base = atomicAdd(&g_total, s[255]);
    __syncthreads();
    if (i < N_NODES) {
        int ro = base + s[t] - v;  // exclusive within block + global base
        g_rowoff[i] = ro;
        g_cursor[i] = ro;
        g_dinv[i] = rsqrtf((float)(v + 1));
    }
}

// Fill CSR slots with {src, precomputed edge norm = dinv[s]*dinv[d]}.
__global__ void fill_kernel() {
    int e = blockIdx.x * blockDim.x + threadIdx.x;
    if (e >= N_EDGES) return;
    int s = g_src[e];
    int d = g_dst[e];
    int pos = atomicAdd(&g_cursor[d], 1);
    float nm = g_dinv[s] * g_dinv[d];
    g_coln[pos] = make_int2(s, __float_as_int(nm));
}

// ---------------------------------------------------------------------------
// FFMA2 GEMM: tile M=64 rows, N=64 cols, K=128; output stored as fp16.
// LAYER1 reads fp32 x; layer2 reads fp16 a1 (+relu).
// ---------------------------------------------------------------------------
#define XD_STRIDE 130
#define GEMM_SMEM (64 * XD_STRIDE * 8 + 128 * 64 * 4)

template <int WSTRIDE, bool RELU, bool LAYER1>
__global__ void __launch_bounds__(256) gemm_kernel(const float* __restrict__ Xin,
                                                   const float* __restrict__ W) {
    extern __shared__ __align__(16) unsigned char smem_raw[];
    unsigned long long* Xd = (unsigned long long*)smem_raw;          // [64][130]
    float* Ws = (float*)(smem_raw + 64 * XD_STRIDE * 8);             // [128][64]

    __half* H = LAYER1 ? g_h1h : g_h2h;

    const int tid = threadIdx.x;
    const int rowBase = blockIdx.x * 64;
    const int colBase = blockIdx.y * 64;

    #pragma unroll
    for (int i = 0; i < 8; i++) {
        int idx = tid + i * 256;            // (row, k4): 64*32
        int row = idx >> 5, k4 = (idx & 31) * 4;
        int grow = min(rowBase + row, N_NODES - 1);
        float4 v;
        if (LAYER1) {
            v = *(const float4*)(Xin + (size_t)grow * 128 + k4);
        } else {
            v = h4_to_f4(*(const uint2*)(g_a1h + (size_t)grow * 128 + k4));
        }
        if (RELU) {
            v.x = fmaxf(v.x, 0.f); v.y = fmaxf(v.y, 0.f);
            v.z = fmaxf(v.z, 0.f); v.w = fmaxf(v.w, 0.f);
        }
        unsigned long long* p = &Xd[row * XD_STRIDE + k4];
        ((ulonglong2*)p)[0] = make_ulonglong2(pack2(v.x), pack2(v.y));
        ((ulonglong2*)p)[1] = make_ulonglong2(pack2(v.z), pack2(v.w));
    }
    #pragma unroll
    for (int i = 0; i < 8; i++) {
        int idx = tid + i * 256;            // (k, c4): 128*16
        int k = idx >> 4, c4 = (idx & 15) * 4;
        *(float4*)&Ws[k * 64 + c4] = *(const float4*)(W + k * WSTRIDE + colBase + c4);
    }
    __syncthreads();

    const int ty = tid >> 4;
    const int tx = tid & 15;
    unsigned long long acc[4][2];
    #pragma unroll
    for (int r = 0; r < 4; r++) { acc[r][0] = 0ull; acc[r][1] = 0ull; }

    const unsigned long long* xb = &Xd[ty * 4 * XD_STRIDE];
    const float* wb = &Ws[tx * 4];

    #pragma unroll 4
    for (int k = 0; k < 128; k++) {
        ulonglong2 w2 = *(const ulonglong2*)(wb + k * 64);
        #pragma unroll
        for (int r = 0; r < 4; r++) {
            unsigned long long xp = xb[r * XD_STRIDE + k];
            FMA2(acc[r][0], xp, w2.x);
            FMA2(acc[r][1], xp, w2.y);
        }
    }

    #pragma unroll
    for (int r = 0; r < 4; r++) {
        int grow = rowBase + ty * 4 + r;
        if (grow < N_NODES) {
            float4 o;
            unpack2(acc[r][0], o.x, o.y);
            unpack2(acc[r][1], o.z, o.w);
            *(uint2*)&H[(size_t)grow * WSTRIDE + colBase + tx * 4] = f4_to_h4(o);
        }
    }
}

// FMA a float4 row into acc with scalar norm
#define ROWFMA(acc, v, nm) \
    acc.x = fmaf(v.x, nm, acc.x); acc.y = fmaf(v.y, nm, acc.y); \
    acc.z = fmaf(v.z, nm, acc.z); acc.w = fmaf(v.w, nm, acc.w)

// ---------------------------------------------------------------------------
// Layer-1 aggregation by fp16 gather (D=128, one node per warp), 4-way ILP.
// Accumulate fp32, write a1 fp16.
// ---------------------------------------------------------------------------
__global__ void agg128_kernel(const float* __restrict__ b) {
    int n = (blockIdx.x * blockDim.x + threadIdx.x) >> 5;
    int l = threadIdx.x & 31;
    if (n >= N_NODES) return;

    int beg = g_rowoff[n];
    int cnt = g_cnt[n];
    float din = g_dinv[n];

    float4 h = h4_to_f4(((const uint2*)(g_h1h + (size_t)n * 128))[l]);
    float4 bb = ((const float4*)b)[l];
    float w = din * din;
    float4 acc;
    acc.x = fmaf(h.x, w, bb.x);
    acc.y = fmaf(h.y, w, bb.y);
    acc.z = fmaf(h.z, w, bb.z);
    acc.w = fmaf(h.w, w, bb.w);

    int i = 0;
    for (; i + 4 <= cnt; i += 4) {
        int2 c0 = g_coln[beg + i];
        int2 c1 = g_coln[beg + i + 1];
        int2 c2 = g_coln[beg + i + 2];
        int2 c3 = g_coln[beg + i + 3];
        uint2 r0 = ldcg2((const uint2*)(g_h1h + (size_t)c0.x * 128) + l);
        uint2 r1 = ldcg2((const uint2*)(g_h1h + (size_t)c1.x * 128) + l);
        uint2 r2 = ldcg2((const uint2*)(g_h1h + (size_t)c2.x * 128) + l);
        uint2 r3 = ldcg2((const uint2*)(g_h1h + (size_t)c3.x * 128) + l);
        float4 v0 = h4_to_f4(r0);
        float4 v1 = h4_to_f4(r1);
        float4 v2 = h4_to_f4(r2);
        float4 v3 = h4_to_f4(r3);
        ROWFMA(acc, v0, __int_as_float(c0.y));
        ROWFMA(acc, v1, __int_as_float(c1.y));
        ROWFMA(acc, v2, __int_as_float(c2.y));
        ROWFMA(acc, v3, __int_as_float(c3.y));
    }
    for (; i < cnt; i++) {
        int2 c0 = g_coln[beg + i];
        float4 v0 = h4_to_f4(ldcg2((const uint2*)(g_h1h + (size_t)c0.x * 128) + l));
        ROWFMA(acc, v0, __int_as_float(c0.y));
    }

    ((uint2*)(g_a1h + (size_t)n * 128))[l] = f4_to_h4(acc);
}

// ---------------------------------------------------------------------------
// Layer-2 fp16 aggregation (D=64, 2 nodes per warp) FUSED with log_softmax.
// ---------------------------------------------------------------------------
__global__ void agg64_softmax_kernel(const float* __restrict__ b,
                                     float* __restrict__ out) {
    int gw = (blockIdx.x * blockDim.x + threadIdx.x) >> 5;
    int lane = threadIdx.x & 31;
    int n = gw * 2 + (lane >> 4);
    int l = lane & 15;
    if (n >= N_NODES) return;

    int beg = g_rowoff[n];
    int cnt = g_cnt[n];
    float din = g_dinv[n];

    float4 h = h4_to_f4(((const uint2*)(g_h2h + (size_t)n * 64))[l]);
    float4 bb = ((const float4*)b)[l];
    float w = din * din;
    float4 acc;
    acc.x = fmaf(h.x, w, bb.x);
    acc.y = fmaf(h.y, w, bb.y);
    acc.z = fmaf(h.z, w, bb.z);
    acc.w = fmaf(h.w, w, bb.w);

    int i = 0;
    for (; i + 4 <= cnt; i += 4) {
        int2 c0 = g_coln[beg + i];
        int2 c1 = g_coln[beg + i + 1];
        int2 c2 = g_coln[beg + i + 2];
        int2 c3 = g_coln[beg + i + 3];
        uint2 r0 = ldcg2((const uint2*)(g_h2h + (size_t)c0.x * 64) + l);
        uint2 r1 = ldcg2((const uint2*)(g_h2h + (size_t)c1.x * 64) + l);
        uint2 r2 = ldcg2((const uint2*)(g_h2h + (size_t)c2.x * 64) + l);
        uint2 r3 = ldcg2((const uint2*)(g_h2h + (size_t)c3.x * 64) + l);
        float4 v0 = h4_to_f4(r0);
        float4 v1 = h4_to_f4(r1);
        float4 v2 = h4_to_f4(r2);
        float4 v3 = h4_to_f4(r3);
        ROWFMA(acc, v0, __int_as_float(c0.y));
        ROWFMA(acc, v1, __int_as_float(c1.y));
        ROWFMA(acc, v2, __int_as_float(c2.y));
        ROWFMA(acc, v3, __int_as_float(c3.y));
    }
    for (; i < cnt; i++) {
        int2 c0 = g_coln[beg + i];
        float4 v0 = h4_to_f4(ldcg2((const uint2*)(g_h2h + (size_t)c0.x * 64) + l));
        ROWFMA(acc, v0, __int_as_float(c0.y));
    }

    // log_softmax over the 64 values of node n (16 lanes x 4)
    float m = fmaxf(fmaxf(acc.x, acc.y), fmaxf(acc.z, acc.w));
    #pragma unroll
    for (int o = 8; o; o >>= 1) m = fmaxf(m, __shfl_xor_sync(0xffffffffu, m, o, 16));
    float s = expf(acc.x - m) + expf(acc.y - m) + expf(acc.z - m) + expf(acc.w - m);
    #pragma unroll
    for (int o = 8; o; o >>= 1) s += __shfl_xor_sync(0xffffffffu, s, o, 16);
    float ls = m + logf(s);

    float4 r;
    r.x = acc.x - ls; r.y = acc.y - ls; r.z = acc.z - ls; r.w = acc.w - ls;
    ((float4*)(out + (size_t)n * 64))[l] = r;
}

// ---------------------------------------------------------------------------
extern "C" void kernel_launch(void* const* d_in, const int* in_sizes, int n_in,
                              void* d_out, int out_size) {
    // Bind inputs by UNIQUE element count (ordering/dtype robust).
    const float* x = nullptr;
    const void* ei = nullptr;
    const float *W1 = nullptr, *b1 = nullptr, *W2 = nullptr, *b2 = nullptr;
    for (int i = 0; i < n_in; i++) {
        switch (in_sizes[i]) {
            case 6400000: x  = (const float*)d_in[i]; break;
            case 1600000: ei = d_in[i]; break;
            case 16384:   W1 = (const float*)d_in[i]; break;
            case 128:     b1 = (const float*)d_in[i]; break;
            case 8192:    W2 = (const float*)d_in[i]; break;
            case 64:      b2 = (const float*)d_in[i]; break;
        }
    }
    float* out = (float*)d_out;

    // One-time host-side resources (no device memory involved).
    static cudaStream_t side = nullptr;
    static cudaEvent_t evFork = nullptr, evJoin = nullptr;
    if (!side) {
        cudaStreamCreateWithFlags(&side, cudaStreamNonBlocking);
        cudaEventCreateWithFlags(&evFork, cudaEventDisableTiming);
        cudaEventCreateWithFlags(&evJoin, cudaEventDisableTiming);
        cudaFuncSetAttribute(gemm_kernel<128, false, true>,
                             cudaFuncAttributeMaxDynamicSharedMemorySize, GEMM_SMEM);
        cudaFuncSetAttribute(gemm_kernel<64, true, false>,
                             cudaFuncAttributeMaxDynamicSharedMemorySize, GEMM_SMEM);
    }

    const int NB = (N_NODES + 255) / 256;  // 196
    const int EB = (N_EDGES + 255) / 256;

    // Fork: CSR build chain on side stream (4 launches), gemm1 on main stream.
    cudaEventRecord(evFork, 0);
    cudaStreamWaitEvent(side, evFork, 0);

    zero_detect_kernel<<<NB, 256, 0, side>>>((const int*)ei);
    decode_count_kernel<<<EB, 256, 0, side>>>(ei);
    alloc_kernel<<<NB, 256, 0, side>>>();
    fill_kernel<<<EB, 256, 0, side>>>();
    cudaEventRecord(evJoin, side);

    gemm_kernel<128, false, true><<<dim3(782, 2), 256, GEMM_SMEM>>>(x, W1);

    // Join: agg128 needs both gemm1 (h1) and the CSR structures.
    cudaStreamWaitEvent(0, evJoin, 0);
    agg128_kernel<<<(N_NODES * 32 + 255) / 256, 256>>>(b1);

    gemm_kernel<64, true, false><<<dim3(782, 1), 256, GEMM_SMEM>>>(nullptr, W2);
    agg64_softmax_kernel<<<(N_NODES * 16 + 255) / 256, 256>>>(b2, out);
}